// round 16
// baseline (speedup 1.0000x reference)
#include <cuda_runtime.h>
#include <cuda_fp16.h>
#include <math.h>

#define B_  2
#define S_  2048
#define D_  1024
#define H_  16
#define HD_ 64
#define NMASK ((size_t)B_ * S_ * S_)

// ---------------- scratch ----------------
__device__ __half g_Qh[(size_t)B_ * S_ * D_];
__device__ __half g_Kh[(size_t)B_ * S_ * D_];
__device__ __half g_Vh[(size_t)B_ * S_ * D_];
__device__ __half g_xh[(size_t)B_ * S_ * D_];     // fp16 copy of x
__device__ __half g_Wqh[D_ * D_];                  // fp16 copies of weights
__device__ __half g_Wkh[D_ * D_];
__device__ __half g_Wvh[D_ * D_];
__device__ unsigned g_mask_bits[NMASK / 32];
__device__ int g_mask_is_int32;

// ---------------- mask dtype detection ----------------
__global__ void detect_mask_kernel(const unsigned int* __restrict__ m) {
    __shared__ int s_ok;
    if (threadIdx.x == 0) s_ok = 1;
    __syncthreads();
    int bad = 0;
#pragma unroll
    for (int i = 0; i < 8; ++i)
        if (m[threadIdx.x * 8 + i] > 1u) bad = 1;
    if (bad) atomicExch(&s_ok, 0);
    __syncthreads();
    if (threadIdx.x == 0) g_mask_is_int32 = s_ok;
}

// ---------------- mask bit-packing ----------------
__global__ void pack_mask_kernel(const void* __restrict__ mask_raw) {
    const int lane = threadIdx.x & 31;
    const size_t warp_g = ((size_t)blockIdx.x * blockDim.x + threadIdx.x) >> 5;
    const size_t base = warp_g * 128;
    if (base >= NMASK) return;
    const int is_int = g_mask_is_int32;
    const int* __restrict__ mi = (const int*)mask_raw;
    const unsigned char* __restrict__ mb = (const unsigned char*)mask_raw;
#pragma unroll
    for (int j = 0; j < 4; ++j) {
        const size_t e = base + (size_t)j * 32 + lane;
        int v = is_int ? mi[e] : (int)mb[e];
        unsigned w = __ballot_sync(0xffffffffu, v != 0);
        if (lane == 0) g_mask_bits[base / 32 + j] = w;
    }
}

// ---------------- helpers ----------------
__device__ __forceinline__ float ex2f(float t) {
    float p;
    asm("ex2.approx.f32 %0, %1;" : "=f"(p) : "f"(t));
    return p;
}
__device__ __forceinline__ float mask_zero(float s, unsigned bit) {
    return __uint_as_float(__float_as_uint(s) & (bit - 1u));
}
__device__ __forceinline__ unsigned smem_u32(const void* p) {
    return (unsigned)__cvta_generic_to_shared(p);
}
__device__ __forceinline__ unsigned pack_h2(float lo, float hi) {
    unsigned u;
    asm("cvt.rn.f16x2.f32 %0, %1, %2;" : "=r"(u) : "f"(hi), "f"(lo));
    return u;
}

#define MMA_F16(c, a0, a1, a2, a3, b0, b1)                                         \
    asm volatile(                                                                  \
        "mma.sync.aligned.m16n8k16.row.col.f32.f16.f16.f32 "                       \
        "{%0,%1,%2,%3}, {%4,%5,%6,%7}, {%8,%9}, {%0,%1,%2,%3};"                    \
        : "+f"((c)[0]), "+f"((c)[1]), "+f"((c)[2]), "+f"((c)[3])                   \
        : "r"(a0), "r"(a1), "r"(a2), "r"(a3), "r"(b0), "r"(b1))

#define LDSM_X2_TRANS(r0, r1, addr)                                               \
    asm volatile("ldmatrix.sync.aligned.m8n8.x2.trans.shared.b16 {%0,%1}, [%2];"  \
                 : "=r"(r0), "=r"(r1) : "r"(addr))

#define LDSM_X4(r0, r1, r2, r3, addr)                                             \
    asm volatile("ldmatrix.sync.aligned.m8n8.x4.shared.b16 {%0,%1,%2,%3}, [%4];"  \
                 : "=r"(r0), "=r"(r1), "=r"(r2), "=r"(r3) : "r"(addr))

#define LDSM_X4_TRANS(r0, r1, r2, r3, addr)                                       \
    asm volatile("ldmatrix.sync.aligned.m8n8.x4.trans.shared.b16 {%0,%1,%2,%3}, [%4];" \
                 : "=r"(r0), "=r"(r1), "=r"(r2), "=r"(r3) : "r"(addr))

#define CP_ASYNC16(dst_u32, src_ptr)                                              \
    asm volatile("cp.async.cg.shared.global [%0], [%1], 16;"                      \
                 :: "r"(dst_u32), "l"(src_ptr))
#define CP_COMMIT() asm volatile("cp.async.commit_group;" ::: "memory")
#define CP_WAIT1()  asm volatile("cp.async.wait_group 1;" ::: "memory")

// ---------------- fp32 -> fp16 conversion (one-time, ~8us total) -------------------
__global__ void f2h_kernel(const float* __restrict__ src, __half* __restrict__ dst,
                           int n4) {
    int i = blockIdx.x * blockDim.x + threadIdx.x;
    if (i < n4) {
        float4 v = ((const float4*)src)[i];
        uint2 w;
        w.x = pack_h2(v.x, v.y);
        w.y = pack_h2(v.z, v.w);
        ((uint2*)dst)[i] = w;
    }
}

// ---------------- QKV projection GEMM: fp16 inputs + cp.async double buffer --------
#define TBM 128
#define TBN 128
#define TBK 32
#define AS_W 40
#define BS_W 136
#define NKT (D_ / TBK)
#define AS_BUF_B (TBM * AS_W * 2)   // 10240 bytes per A buffer
#define BS_BUF_B (TBK * BS_W * 2)   // 8704 bytes per B buffer

__global__ __launch_bounds__(256) void qkv_gemm_tc_kernel(
    const float* __restrict__ bq, const float* __restrict__ bk,
    const float* __restrict__ bv)
{
    const __half* W; const float* bias; __half* C; float oscale;
    if (blockIdx.z == 0)      { W = g_Wqh; bias = bq; C = g_Qh; oscale = 0.125f * 1.44269504088896341f; }
    else if (blockIdx.z == 1) { W = g_Wkh; bias = bk; C = g_Kh; oscale = 1.0f; }
    else                      { W = g_Wvh; bias = bv; C = g_Vh; oscale = 1.0f; }

    __shared__ __half As[2][TBM][AS_W];
    __shared__ __half Bs[2][TBK][BS_W];

    const int tid    = threadIdx.x;
    const int lane   = tid & 31;
    const int wid    = tid >> 5;
    const int warp_m = wid & 1;
    const int warp_n = wid >> 1;
    const int m0     = blockIdx.y * TBM;
    const int n0     = blockIdx.x * TBN;

    const int r = lane >> 2;
    const int c = lane & 3;
    const unsigned bs_l = smem_u32(&Bs[0][lane & 15][warp_n * 32]);

    // cp.async mappings:
    // A tile: 128 rows x 64B = 512 chunks; thread covers chunks tid, tid+256
    const int a_row = tid >> 2;          // 0..63, second chunk row +64
    const int a_ch  = (tid & 3) * 8;     // half offset within row
    // B tile: 32 rows x 256B = 512 chunks; thread covers chunks tid, tid+256
    const int b_row = tid >> 4;          // 0..15, second chunk row +16
    const int b_ch  = (tid & 15) * 8;

    const unsigned ad0 = smem_u32(&As[0][a_row][a_ch]);
    const unsigned ad1 = ad0 + 64 * AS_W * 2;
    const unsigned bd0 = smem_u32(&Bs[0][b_row][b_ch]);
    const unsigned bd1 = bd0 + 16 * BS_W * 2;

    const __half* asrc0 = g_xh + (size_t)(m0 + a_row) * D_ + a_ch;
    const __half* asrc1 = asrc0 + (size_t)64 * D_;
    const __half* bsrc0 = W + (size_t)b_row * D_ + n0 + b_ch;
    const __half* bsrc1 = bsrc0 + (size_t)16 * D_;

    // prologue: tile0 -> buf0, tile1 -> buf1
    CP_ASYNC16(ad0, asrc0);
    CP_ASYNC16(ad1, asrc1);
    CP_ASYNC16(bd0, bsrc0);
    CP_ASYNC16(bd1, bsrc1);
    CP_COMMIT();
    CP_ASYNC16(ad0 + AS_BUF_B, asrc0 + TBK);
    CP_ASYNC16(ad1 + AS_BUF_B, asrc1 + TBK);
    CP_ASYNC16(bd0 + BS_BUF_B, bsrc0 + (size_t)TBK * D_);
    CP_ASYNC16(bd1 + BS_BUF_B, bsrc1 + (size_t)TBK * D_);
    CP_COMMIT();

    float acc[4][4][4];
#pragma unroll
    for (int mi = 0; mi < 4; ++mi)
#pragma unroll
        for (int nj = 0; nj < 4; ++nj)
#pragma unroll
            for (int q = 0; q < 4; ++q) acc[mi][nj][q] = 0.0f;

    for (int t = 0; t < NKT; ++t) {
        const int cb = t & 1;
        CP_WAIT1();
        __syncthreads();

        const unsigned bs_cur = bs_l + (unsigned)(cb * BS_BUF_B);
#pragma unroll
        for (int ks = 0; ks < 2; ++ks) {
            const int k = ks * 16;
            unsigned a[4][4], b[4][2];
#pragma unroll
            for (int mi = 0; mi < 4; ++mi) {
                const int rb = warp_m * 64 + mi * 16;
                a[mi][0] = *(const unsigned*)&As[cb][rb + r    ][k + 2 * c    ];
                a[mi][1] = *(const unsigned*)&As[cb][rb + r + 8][k + 2 * c    ];
                a[mi][2] = *(const unsigned*)&As[cb][rb + r    ][k + 2 * c + 8];
                a[mi][3] = *(const unsigned*)&As[cb][rb + r + 8][k + 2 * c + 8];
            }
#pragma unroll
            for (int nj = 0; nj < 4; ++nj) {
                LDSM_X2_TRANS(b[nj][0], b[nj][1],
                              bs_cur + (unsigned)(ks * 16 * (BS_W * 2) + nj * 16));
            }
#pragma unroll
            for (int mi = 0; mi < 4; ++mi)
#pragma unroll
                for (int nj = 0; nj < 4; ++nj)
                    MMA_F16(acc[mi][nj], a[mi][0], a[mi][1], a[mi][2], a[mi][3],
                            b[nj][0], b[nj][1]);
        }
        __syncthreads();

        // refill just-freed buffer with tile t+2
        if (t + 2 < NKT) {
            const int kf = (t + 2) * TBK;
            CP_ASYNC16(ad0 + (unsigned)(cb * AS_BUF_B), asrc0 + kf);
            CP_ASYNC16(ad1 + (unsigned)(cb * AS_BUF_B), asrc1 + kf);
            CP_ASYNC16(bd0 + (unsigned)(cb * BS_BUF_B), bsrc0 + (size_t)kf * D_);
            CP_ASYNC16(bd1 + (unsigned)(cb * BS_BUF_B), bsrc1 + (size_t)kf * D_);
        }
        CP_COMMIT();
    }

#pragma unroll
    for (int mi = 0; mi < 4; ++mi) {
#pragma unroll
        for (int nj = 0; nj < 4; ++nj) {
            const int row0 = m0 + warp_m * 64 + mi * 16 + r;
            const int col  = n0 + warp_n * 32 + nj * 8 + 2 * c;
            float2 bb = *(const float2*)&bias[col];
            *(unsigned*)&C[(size_t)row0 * D_ + col] =
                pack_h2((acc[mi][nj][0] + bb.x) * oscale,
                        (acc[mi][nj][1] + bb.y) * oscale);
            *(unsigned*)&C[(size_t)(row0 + 8) * D_ + col] =
                pack_h2((acc[mi][nj][2] + bb.x) * oscale,
                        (acc[mi][nj][3] + bb.y) * oscale);
        }
    }
}

// ---------------- fp16 flash attention (R15, measured 124us — unchanged) -----------
#define AT_BM 128
#define AT_BK 64
#define ROW_H 72
#define KVH   (AT_BK * ROW_H)
#define KVB   (KVH * 2)
#define NT    (S_ / AT_BK)

__global__ __launch_bounds__(256, 2) void attn_tc_kernel(float* __restrict__ out)
{
    extern __shared__ __half smh[];
    __half (*Qs)[ROW_H]  = (__half(*)[ROW_H])smh;
    __half (*Kb0)[ROW_H] = (__half(*)[ROW_H])(smh + AT_BM * ROW_H);
    __half (*Vb0)[ROW_H] = (__half(*)[ROW_H])(smh + AT_BM * ROW_H + 2 * KVH);

    const int tid  = threadIdx.x;
    const int lane = tid & 31;
    const int wid  = tid >> 5;
    const int r    = lane >> 2;
    const int c    = lane & 3;
    const int m0   = wid * 16;
    const int q0   = blockIdx.x * AT_BM;
    const int h    = blockIdx.y;
    const int b    = blockIdx.z;

    const unsigned qa_l = smem_u32(
        &Qs[m0 + ((lane >> 3) & 1) * 8 + (lane & 7)][((lane >> 4) & 1) * 8]);
    const unsigned kb_l = smem_u32(
        &Kb0[((lane >> 4) & 1) * 8 + (lane & 7)][((lane >> 3) & 1) * 8]);
    const unsigned vb_l = smem_u32(&Vb0[lane & 15][((lane >> 4) & 1) * 8]);

    const int row0 = tid >> 3;
    const int col8 = (tid & 7) * 8;
    const __half* Kg0 = g_Kh + ((size_t)b * S_) * D_ + h * HD_;
    const __half* Vg0 = g_Vh + ((size_t)b * S_) * D_ + h * HD_;

    const unsigned kd0 = smem_u32(&Kb0[row0][col8]);
    const unsigned kd1 = smem_u32(&Kb0[row0 + 32][col8]);
    const unsigned vd0 = smem_u32(&Vb0[row0][col8]);
    const unsigned vd1 = smem_u32(&Vb0[row0 + 32][col8]);
    const size_t goff0 = (size_t)row0 * D_ + col8;
    const size_t goff1 = (size_t)(row0 + 32) * D_ + col8;

    {
        const __half* Qg = g_Qh + ((size_t)b * S_ + q0) * D_ + h * HD_;
#pragma unroll
        for (int it = 0; it < 4; ++it) {
            int u   = tid + it * 256;
            int row = u >> 3;
            int cc  = (u & 7) * 8;
            *(uint4*)&Qs[row][cc] = *(const uint4*)(Qg + (size_t)row * D_ + cc);
        }
    }
    CP_ASYNC16(kd0, Kg0 + goff0);
    CP_ASYNC16(kd1, Kg0 + goff1);
    CP_ASYNC16(vd0, Vg0 + goff0);
    CP_ASYNC16(vd1, Vg0 + goff1);
    CP_COMMIT();
    {
        const __half* Kg = Kg0 + (size_t)AT_BK * D_;
        const __half* Vg = Vg0 + (size_t)AT_BK * D_;
        CP_ASYNC16(kd0 + KVB, Kg + goff0);
        CP_ASYNC16(kd1 + KVB, Kg + goff1);
        CP_ASYNC16(vd0 + KVB, Vg + goff0);
        CP_ASYNC16(vd1 + KVB, Vg + goff1);
        CP_COMMIT();
    }
    __syncthreads();

    unsigned qa[4][4];
#pragma unroll
    for (int kk = 0; kk < 4; ++kk)
        LDSM_X4(qa[kk][0], qa[kk][1], qa[kk][2], qa[kk][3],
                qa_l + (unsigned)(kk * 32));

    const size_t mwrow0 = ((size_t)b * S_ + q0 + m0 + r) * (S_ / 32);
    const size_t mwrow1 = mwrow0 + 8 * (size_t)(S_ / 32);

    float o[8][4];
    float rs0 = 0.0f, rs1 = 0.0f;
#pragma unroll
    for (int nt = 0; nt < 8; ++nt)
#pragma unroll
        for (int q = 0; q < 4; ++q) o[nt][q] = 0.0f;

    for (int kt = 0; kt < NT; ++kt) {
        const unsigned bufb = (unsigned)(kt & 1) * KVB;

        CP_WAIT1();
        __syncthreads();

        float s[8][4];
#pragma unroll
        for (int nt = 0; nt < 8; ++nt)
#pragma unroll
            for (int q = 0; q < 4; ++q) s[nt][q] = 0.0f;

#pragma unroll
        for (int kk = 0; kk < 4; ++kk) {
#pragma unroll
            for (int p = 0; p < 4; ++p) {
                unsigned b0, b1, b2, b3;
                LDSM_X4(b0, b1, b2, b3,
                        kb_l + bufb + (unsigned)(p * 16 * (ROW_H * 2) + kk * 32));
                MMA_F16(s[2 * p],     qa[kk][0], qa[kk][1], qa[kk][2], qa[kk][3], b0, b1);
                MMA_F16(s[2 * p + 1], qa[kk][0], qa[kk][1], qa[kk][2], qa[kk][3], b2, b3);
            }
        }

        {
            const int k0 = kt * AT_BK;
            const uint2 w0 = *(const uint2*)&g_mask_bits[mwrow0 + (k0 >> 5)];
            const uint2 w1 = *(const uint2*)&g_mask_bits[mwrow1 + (k0 >> 5)];
#pragma unroll
            for (int nt = 0; nt < 8; ++nt) {
                const unsigned ws0 = (nt < 4) ? w0.x : w0.y;
                const unsigned ws1 = (nt < 4) ? w1.x : w1.y;
                const int sh = (nt * 8 + 2 * c) & 31;
                s[nt][0] = mask_zero(s[nt][0], (ws0 >> sh) & 1u);
                s[nt][1] = mask_zero(s[nt][1], (ws0 >> (sh + 1)) & 1u);
                s[nt][2] = mask_zero(s[nt][2], (ws1 >> sh) & 1u);
                s[nt][3] = mask_zero(s[nt][3], (ws1 >> (sh + 1)) & 1u);
            }
        }

        unsigned ph[8][2];
#pragma unroll
        for (int nt = 0; nt < 8; ++nt) {
            float p0 = ex2f(s[nt][0]);
            float p1 = ex2f(s[nt][1]);
            float p2 = ex2f(s[nt][2]);
            float p3 = ex2f(s[nt][3]);
            rs0 += p0 + p1;
            rs1 += p2 + p3;
            ph[nt][0] = pack_h2(p0, p1);
            ph[nt][1] = pack_h2(p2, p3);
        }

#pragma unroll
        for (int kk = 0; kk < 4; ++kk) {
            const int kb = kk * 16;
            const unsigned a0 = ph[2 * kk][0];
            const unsigned a1 = ph[2 * kk][1];
            const unsigned a2 = ph[2 * kk + 1][0];
            const unsigned a3 = ph[2 * kk + 1][1];
#pragma unroll
            for (int p = 0; p < 4; ++p) {
                unsigned b0, b1, b2, b3;
                LDSM_X4_TRANS(b0, b1, b2, b3,
                              vb_l + bufb + (unsigned)(kb * (ROW_H * 2) + p * 32));
                MMA_F16(o[2 * p],     a0, a1, a2, a3, b0, b1);
                MMA_F16(o[2 * p + 1], a0, a1, a2, a3, b2, b3);
            }
        }

        __syncthreads();

        if (kt + 2 < NT) {
            const __half* Kg = Kg0 + (size_t)(kt + 2) * AT_BK * D_;
            const __half* Vg = Vg0 + (size_t)(kt + 2) * AT_BK * D_;
            CP_ASYNC16(kd0 + bufb, Kg + goff0);
            CP_ASYNC16(kd1 + bufb, Kg + goff1);
            CP_ASYNC16(vd0 + bufb, Vg + goff0);
            CP_ASYNC16(vd1 + bufb, Vg + goff1);
        }
        CP_COMMIT();
    }

    rs0 += __shfl_xor_sync(0xffffffffu, rs0, 1);
    rs0 += __shfl_xor_sync(0xffffffffu, rs0, 2);
    rs1 += __shfl_xor_sync(0xffffffffu, rs1, 1);
    rs1 += __shfl_xor_sync(0xffffffffu, rs1, 2);
    const float inv0 = 1.0f / rs0;
    const float inv1 = 1.0f / rs1;

    float* og0 = out + ((size_t)b * S_ + q0 + m0 + r) * D_ + h * HD_;
    float* og1 = og0 + 8 * (size_t)D_;
#pragma unroll
    for (int nt = 0; nt < 8; ++nt) {
        const int col = nt * 8 + 2 * c;
        float2 w0; w0.x = o[nt][0] * inv0; w0.y = o[nt][1] * inv0;
        float2 w1; w1.x = o[nt][2] * inv1; w1.y = o[nt][3] * inv1;
        *(float2*)&og0[col] = w0;
        *(float2*)&og1[col] = w1;
    }
}

// ---------------- launch ----------------
extern "C" void kernel_launch(void* const* d_in, const int* in_sizes, int n_in,
                              void* d_out, int out_size) {
    (void)in_sizes; (void)n_in; (void)out_size;
    const float* x    = (const float*)d_in[0];
    const void*  mask = d_in[1];
    const float* Wq   = (const float*)d_in[2];
    const float* bq   = (const float*)d_in[3];
    const float* Wk   = (const float*)d_in[4];
    const float* bk   = (const float*)d_in[5];
    const float* Wv   = (const float*)d_in[6];
    const float* bv   = (const float*)d_in[7];
    float* out = (float*)d_out;

    detect_mask_kernel<<<1, 256>>>((const unsigned int*)mask);

    {
        const int warps = (int)(NMASK / 128);
        pack_mask_kernel<<<(warps * 32 + 255) / 256, 256>>>(mask);
    }

    // one-time fp32 -> fp16 conversions (device-symbol destinations)
    {
        __half* dxh;  cudaGetSymbolAddress((void**)&dxh,  g_xh);
        __half* dwq;  cudaGetSymbolAddress((void**)&dwq,  g_Wqh);
        __half* dwk;  cudaGetSymbolAddress((void**)&dwk,  g_Wkh);
        __half* dwv;  cudaGetSymbolAddress((void**)&dwv,  g_Wvh);
        const int nx4 = (int)((size_t)B_ * S_ * D_ / 4);
        const int nw4 = D_ * D_ / 4;
        f2h_kernel<<<(nx4 + 255) / 256, 256>>>(x,  dxh, nx4);
        f2h_kernel<<<(nw4 + 255) / 256, 256>>>(Wq, dwq, nw4);
        f2h_kernel<<<(nw4 + 255) / 256, 256>>>(Wk, dwk, nw4);
        f2h_kernel<<<(nw4 + 255) / 256, 256>>>(Wv, dwv, nw4);
    }

    dim3 ggrid(D_ / TBN, (B_ * S_) / TBM, 3);
    qkv_gemm_tc_kernel<<<ggrid, 256>>>(bq, bk, bv);

    const int smem_bytes = (AT_BM * ROW_H + 4 * KVH) * (int)sizeof(__half);
    cudaFuncSetAttribute(attn_tc_kernel, cudaFuncAttributeMaxDynamicSharedMemorySize, smem_bytes);
    dim3 agrid(S_ / AT_BM, H_, B_);
    attn_tc_kernel<<<agrid, 256, smem_bytes>>>(out);
}

// round 17
// speedup vs baseline: 1.0721x; 1.0721x over previous
#include <cuda_runtime.h>
#include <cuda_fp16.h>
#include <math.h>

#define B_  2
#define S_  2048
#define D_  1024
#define H_  16
#define HD_ 64
#define NMASK ((size_t)B_ * S_ * S_)

// ---------------- scratch ----------------
__device__ __half g_Qh[(size_t)B_ * S_ * D_];
__device__ __half g_Kh[(size_t)B_ * S_ * D_];
__device__ __half g_Vh[(size_t)B_ * S_ * D_];
__device__ unsigned g_mask_bits[NMASK / 32];
__device__ int g_mask_is_int32;

// ---------------- mask dtype detection ----------------
__global__ void detect_mask_kernel(const unsigned int* __restrict__ m) {
    __shared__ int s_ok;
    if (threadIdx.x == 0) s_ok = 1;
    __syncthreads();
    int bad = 0;
#pragma unroll
    for (int i = 0; i < 8; ++i)
        if (m[threadIdx.x * 8 + i] > 1u) bad = 1;
    if (bad) atomicExch(&s_ok, 0);
    __syncthreads();
    if (threadIdx.x == 0) g_mask_is_int32 = s_ok;
}

// ---------------- mask bit-packing ----------------
__global__ void pack_mask_kernel(const void* __restrict__ mask_raw) {
    const int lane = threadIdx.x & 31;
    const size_t warp_g = ((size_t)blockIdx.x * blockDim.x + threadIdx.x) >> 5;
    const size_t base = warp_g * 128;
    if (base >= NMASK) return;
    const int is_int = g_mask_is_int32;
    const int* __restrict__ mi = (const int*)mask_raw;
    const unsigned char* __restrict__ mb = (const unsigned char*)mask_raw;
#pragma unroll
    for (int j = 0; j < 4; ++j) {
        const size_t e = base + (size_t)j * 32 + lane;
        int v = is_int ? mi[e] : (int)mb[e];
        unsigned w = __ballot_sync(0xffffffffu, v != 0);
        if (lane == 0) g_mask_bits[base / 32 + j] = w;
    }
}

// ---------------- helpers ----------------
__device__ __forceinline__ float ex2f(float t) {
    float p;
    asm("ex2.approx.f32 %0, %1;" : "=f"(p) : "f"(t));
    return p;
}
__device__ __forceinline__ float mask_zero(float s, unsigned bit) {
    return __uint_as_float(__float_as_uint(s) & (bit - 1u));
}
__device__ __forceinline__ unsigned smem_u32(const void* p) {
    return (unsigned)__cvta_generic_to_shared(p);
}
__device__ __forceinline__ unsigned pack_h2(float lo, float hi) {
    unsigned u;
    asm("cvt.rn.f16x2.f32 %0, %1, %2;" : "=r"(u) : "f"(hi), "f"(lo));
    return u;
}

#define MMA_F16(c, a0, a1, a2, a3, b0, b1)                                         \
    asm volatile(                                                                  \
        "mma.sync.aligned.m16n8k16.row.col.f32.f16.f16.f32 "                       \
        "{%0,%1,%2,%3}, {%4,%5,%6,%7}, {%8,%9}, {%0,%1,%2,%3};"                    \
        : "+f"((c)[0]), "+f"((c)[1]), "+f"((c)[2]), "+f"((c)[3])                   \
        : "r"(a0), "r"(a1), "r"(a2), "r"(a3), "r"(b0), "r"(b1))

#define LDSM_X2_TRANS(r0, r1, addr)                                               \
    asm volatile("ldmatrix.sync.aligned.m8n8.x2.trans.shared.b16 {%0,%1}, [%2];"  \
                 : "=r"(r0), "=r"(r1) : "r"(addr))

#define LDSM_X4(r0, r1, r2, r3, addr)                                             \
    asm volatile("ldmatrix.sync.aligned.m8n8.x4.shared.b16 {%0,%1,%2,%3}, [%4];"  \
                 : "=r"(r0), "=r"(r1), "=r"(r2), "=r"(r3) : "r"(addr))

#define LDSM_X4_TRANS(r0, r1, r2, r3, addr)                                       \
    asm volatile("ldmatrix.sync.aligned.m8n8.x4.trans.shared.b16 {%0,%1,%2,%3}, [%4];" \
                 : "=r"(r0), "=r"(r1), "=r"(r2), "=r"(r3) : "r"(addr))

#define CP_ASYNC16(dst_u32, src_ptr)                                              \
    asm volatile("cp.async.cg.shared.global [%0], [%1], 16;"                      \
                 :: "r"(dst_u32), "l"(src_ptr))
#define CP_COMMIT() asm volatile("cp.async.commit_group;" ::: "memory")
#define CP_WAIT1()  asm volatile("cp.async.wait_group 1;" ::: "memory")

// ---------------- QKV projection GEMM (R13 pipeline + LDSM.x4 A-fragments) ---------
#define TBM 128
#define TBN 128
#define TBK 32
#define AS_W 40
#define BS_W 136
#define NKT (D_ / TBK)
#define AS_BUF_B (TBM * AS_W * 2)
#define BS_BUF_B (TBK * BS_W * 2)

__global__ __launch_bounds__(256) void qkv_gemm_tc_kernel(
    const float* __restrict__ x,
    const float* __restrict__ Wq, const float* __restrict__ bq,
    const float* __restrict__ Wk, const float* __restrict__ bk,
    const float* __restrict__ Wv, const float* __restrict__ bv)
{
    const float* W; const float* bias; __half* C; float oscale;
    if (blockIdx.z == 0)      { W = Wq; bias = bq; C = g_Qh; oscale = 0.125f * 1.44269504088896341f; }
    else if (blockIdx.z == 1) { W = Wk; bias = bk; C = g_Kh; oscale = 1.0f; }
    else                      { W = Wv; bias = bv; C = g_Vh; oscale = 1.0f; }

    __shared__ __half As[2][TBM][AS_W];
    __shared__ __half Bs[2][TBK][BS_W];

    const int tid    = threadIdx.x;
    const int lane   = tid & 31;
    const int wid    = tid >> 5;
    const int warp_m = wid & 1;
    const int warp_n = wid >> 1;
    const int m0     = blockIdx.y * TBM;
    const int n0     = blockIdx.x * TBN;

    const int a_row = tid >> 3;
    const int a_kq  = (tid & 7) * 4;
    const int b_row = tid >> 5;
    const int b_nq  = (tid & 31) * 4;

    const int r = lane >> 2;
    const int c = lane & 3;
    const unsigned bs_l = smem_u32(&Bs[0][lane & 15][warp_n * 32]);
    // ldmatrix.x4 base for A fragments (same lane mapping validated on attention Q)
    const unsigned as_l = smem_u32(
        &As[0][warp_m * 64 + ((lane >> 3) & 1) * 8 + (lane & 7)][((lane >> 4) & 1) * 8]);

    float4 a_st[4], b_st[4];

#pragma unroll
    for (int it = 0; it < 4; ++it) {
        a_st[it] = *(const float4*)&x[(size_t)(m0 + a_row + 32 * it) * D_ + a_kq];
        b_st[it] = *(const float4*)&W[(size_t)(b_row + 8 * it) * D_ + n0 + b_nq];
    }
#pragma unroll
    for (int it = 0; it < 4; ++it) {
        *(unsigned*)&As[0][a_row + 32 * it][a_kq]     = pack_h2(a_st[it].x, a_st[it].y);
        *(unsigned*)&As[0][a_row + 32 * it][a_kq + 2] = pack_h2(a_st[it].z, a_st[it].w);
        *(unsigned*)&Bs[0][b_row + 8 * it][b_nq]      = pack_h2(b_st[it].x, b_st[it].y);
        *(unsigned*)&Bs[0][b_row + 8 * it][b_nq + 2]  = pack_h2(b_st[it].z, b_st[it].w);
    }
#pragma unroll
    for (int it = 0; it < 4; ++it) {
        a_st[it] = *(const float4*)&x[(size_t)(m0 + a_row + 32 * it) * D_ + TBK + a_kq];
        b_st[it] = *(const float4*)&W[(size_t)(TBK + b_row + 8 * it) * D_ + n0 + b_nq];
    }
    __syncthreads();

    float acc[4][4][4];
#pragma unroll
    for (int mi = 0; mi < 4; ++mi)
#pragma unroll
        for (int nj = 0; nj < 4; ++nj)
#pragma unroll
            for (int q = 0; q < 4; ++q) acc[mi][nj][q] = 0.0f;

    for (int t = 0; t < NKT; ++t) {
        if (t + 1 < NKT) {
            const int nb = (t + 1) & 1;
#pragma unroll
            for (int it = 0; it < 4; ++it) {
                *(unsigned*)&As[nb][a_row + 32 * it][a_kq]     = pack_h2(a_st[it].x, a_st[it].y);
                *(unsigned*)&As[nb][a_row + 32 * it][a_kq + 2] = pack_h2(a_st[it].z, a_st[it].w);
                *(unsigned*)&Bs[nb][b_row + 8 * it][b_nq]      = pack_h2(b_st[it].x, b_st[it].y);
                *(unsigned*)&Bs[nb][b_row + 8 * it][b_nq + 2]  = pack_h2(b_st[it].z, b_st[it].w);
            }
        }
        if (t + 2 < NKT) {
            const int kf = (t + 2) * TBK;
#pragma unroll
            for (int it = 0; it < 4; ++it) {
                a_st[it] = *(const float4*)&x[(size_t)(m0 + a_row + 32 * it) * D_ + kf + a_kq];
                b_st[it] = *(const float4*)&W[(size_t)(kf + b_row + 8 * it) * D_ + n0 + b_nq];
            }
        }

        const int cb = t & 1;
        const unsigned bs_cur = bs_l + (unsigned)(cb * BS_BUF_B);
        const unsigned as_cur = as_l + (unsigned)(cb * AS_BUF_B);
#pragma unroll
        for (int ks = 0; ks < 2; ++ks) {
            unsigned a[4][4], b[4][2];
#pragma unroll
            for (int mi = 0; mi < 4; ++mi) {
                LDSM_X4(a[mi][0], a[mi][1], a[mi][2], a[mi][3],
                        as_cur + (unsigned)(mi * 16 * (AS_W * 2) + ks * 32));
            }
#pragma unroll
            for (int nj = 0; nj < 4; ++nj) {
                LDSM_X2_TRANS(b[nj][0], b[nj][1],
                              bs_cur + (unsigned)(ks * 16 * (BS_W * 2) + nj * 16));
            }
#pragma unroll
            for (int mi = 0; mi < 4; ++mi)
#pragma unroll
                for (int nj = 0; nj < 4; ++nj)
                    MMA_F16(acc[mi][nj], a[mi][0], a[mi][1], a[mi][2], a[mi][3],
                            b[nj][0], b[nj][1]);
        }
        __syncthreads();
    }

#pragma unroll
    for (int mi = 0; mi < 4; ++mi) {
#pragma unroll
        for (int nj = 0; nj < 4; ++nj) {
            const int row0 = m0 + warp_m * 64 + mi * 16 + r;
            const int col  = n0 + warp_n * 32 + nj * 8 + 2 * c;
            float2 bb = *(const float2*)&bias[col];
            *(unsigned*)&C[(size_t)row0 * D_ + col] =
                pack_h2((acc[mi][nj][0] + bb.x) * oscale,
                        (acc[mi][nj][1] + bb.y) * oscale);
            *(unsigned*)&C[(size_t)(row0 + 8) * D_ + col] =
                pack_h2((acc[mi][nj][2] + bb.x) * oscale,
                        (acc[mi][nj][3] + bb.y) * oscale);
        }
    }
}

// ---------------- fp16 flash attention: 3-buffer K/V ring, ONE barrier per tile ----
#define AT_BM 128
#define AT_BK 64
#define ROW_H 72
#define KVH   (AT_BK * ROW_H)
#define KVB   (KVH * 2)
#define NT    (S_ / AT_BK)

__global__ __launch_bounds__(256, 2) void attn_tc_kernel(float* __restrict__ out)
{
    extern __shared__ __half smh[];
    __half (*Qs)[ROW_H]  = (__half(*)[ROW_H])smh;
    __half (*Kb0)[ROW_H] = (__half(*)[ROW_H])(smh + AT_BM * ROW_H);            // 3 K bufs
    __half (*Vb0)[ROW_H] = (__half(*)[ROW_H])(smh + AT_BM * ROW_H + 3 * KVH);  // 3 V bufs

    const int tid  = threadIdx.x;
    const int lane = tid & 31;
    const int wid  = tid >> 5;
    const int r    = lane >> 2;
    const int c    = lane & 3;
    const int m0   = wid * 16;
    const int q0   = blockIdx.x * AT_BM;
    const int h    = blockIdx.y;
    const int b    = blockIdx.z;

    const unsigned qa_l = smem_u32(
        &Qs[m0 + ((lane >> 3) & 1) * 8 + (lane & 7)][((lane >> 4) & 1) * 8]);
    const unsigned kb_l = smem_u32(
        &Kb0[((lane >> 4) & 1) * 8 + (lane & 7)][((lane >> 3) & 1) * 8]);
    const unsigned vb_l = smem_u32(&Vb0[lane & 15][((lane >> 4) & 1) * 8]);

    const int row0 = tid >> 3;
    const int col8 = (tid & 7) * 8;
    const __half* Kg0 = g_Kh + ((size_t)b * S_) * D_ + h * HD_;
    const __half* Vg0 = g_Vh + ((size_t)b * S_) * D_ + h * HD_;

    const unsigned kd0 = smem_u32(&Kb0[row0][col8]);
    const unsigned kd1 = smem_u32(&Kb0[row0 + 32][col8]);
    const unsigned vd0 = smem_u32(&Vb0[row0][col8]);
    const unsigned vd1 = smem_u32(&Vb0[row0 + 32][col8]);
    const size_t goff0 = (size_t)row0 * D_ + col8;
    const size_t goff1 = (size_t)(row0 + 32) * D_ + col8;

    // prologue: Q tile + async K/V tiles 0 -> buf0, 1 -> buf1
    {
        const __half* Qg = g_Qh + ((size_t)b * S_ + q0) * D_ + h * HD_;
#pragma unroll
        for (int it = 0; it < 4; ++it) {
            int u   = tid + it * 256;
            int row = u >> 3;
            int cc  = (u & 7) * 8;
            *(uint4*)&Qs[row][cc] = *(const uint4*)(Qg + (size_t)row * D_ + cc);
        }
    }
    CP_ASYNC16(kd0, Kg0 + goff0);
    CP_ASYNC16(kd1, Kg0 + goff1);
    CP_ASYNC16(vd0, Vg0 + goff0);
    CP_ASYNC16(vd1, Vg0 + goff1);
    CP_COMMIT();
    {
        const __half* Kg = Kg0 + (size_t)AT_BK * D_;
        const __half* Vg = Vg0 + (size_t)AT_BK * D_;
        CP_ASYNC16(kd0 + KVB, Kg + goff0);
        CP_ASYNC16(kd1 + KVB, Kg + goff1);
        CP_ASYNC16(vd0 + KVB, Vg + goff0);
        CP_ASYNC16(vd1 + KVB, Vg + goff1);
        CP_COMMIT();
    }
    __syncthreads();   // Qs visible

    unsigned qa[4][4];
#pragma unroll
    for (int kk = 0; kk < 4; ++kk)
        LDSM_X4(qa[kk][0], qa[kk][1], qa[kk][2], qa[kk][3],
                qa_l + (unsigned)(kk * 32));

    const size_t mwrow0 = ((size_t)b * S_ + q0 + m0 + r) * (S_ / 32);
    const size_t mwrow1 = mwrow0 + 8 * (size_t)(S_ / 32);

    float o[8][4];
    float rs0 = 0.0f, rs1 = 0.0f;
#pragma unroll
    for (int nt = 0; nt < 8; ++nt)
#pragma unroll
        for (int q = 0; q < 4; ++q) o[nt][q] = 0.0f;

    int bi = 0;   // ring buffer index of current tile
    for (int kt = 0; kt < NT; ++kt) {
        const unsigned bufb = (unsigned)bi * KVB;

        CP_WAIT1();        // tile kt's copies complete (kt+1 still in flight)
        __syncthreads();   // ONE barrier per tile: also releases buf (kt+2)%3
                           // (its readers finished in iteration kt-1)

        // ---- QK^T
        float s[8][4];
#pragma unroll
        for (int nt = 0; nt < 8; ++nt)
#pragma unroll
            for (int q = 0; q < 4; ++q) s[nt][q] = 0.0f;

#pragma unroll
        for (int kk = 0; kk < 4; ++kk) {
#pragma unroll
            for (int p = 0; p < 4; ++p) {
                unsigned b0, b1, b2, b3;
                LDSM_X4(b0, b1, b2, b3,
                        kb_l + bufb + (unsigned)(p * 16 * (ROW_H * 2) + kk * 32));
                MMA_F16(s[2 * p],     qa[kk][0], qa[kk][1], qa[kk][2], qa[kk][3], b0, b1);
                MMA_F16(s[2 * p + 1], qa[kk][0], qa[kk][1], qa[kk][2], qa[kk][3], b2, b3);
            }
        }

        // refill buffer (bi+2)%3 with tile kt+2 — its readers passed the barrier above
        {
            int bn = bi + 2; if (bn >= 3) bn -= 3;
            if (kt + 2 < NT) {
                const unsigned nb = (unsigned)bn * KVB;
                const __half* Kg = Kg0 + (size_t)(kt + 2) * AT_BK * D_;
                const __half* Vg = Vg0 + (size_t)(kt + 2) * AT_BK * D_;
                CP_ASYNC16(kd0 + nb, Kg + goff0);
                CP_ASYNC16(kd1 + nb, Kg + goff1);
                CP_ASYNC16(vd0 + nb, Vg + goff0);
                CP_ASYNC16(vd1 + nb, Vg + goff1);
            }
            CP_COMMIT();
        }

        // ---- branchless mask (ref quirk: masked scores -> 0 BEFORE softmax)
        {
            const int k0 = kt * AT_BK;
            const uint2 w0 = *(const uint2*)&g_mask_bits[mwrow0 + (k0 >> 5)];
            const uint2 w1 = *(const uint2*)&g_mask_bits[mwrow1 + (k0 >> 5)];
#pragma unroll
            for (int nt = 0; nt < 8; ++nt) {
                const unsigned ws0 = (nt < 4) ? w0.x : w0.y;
                const unsigned ws1 = (nt < 4) ? w1.x : w1.y;
                const int sh = (nt * 8 + 2 * c) & 31;
                s[nt][0] = mask_zero(s[nt][0], (ws0 >> sh) & 1u);
                s[nt][1] = mask_zero(s[nt][1], (ws0 >> (sh + 1)) & 1u);
                s[nt][2] = mask_zero(s[nt][2], (ws1 >> sh) & 1u);
                s[nt][3] = mask_zero(s[nt][3], (ws1 >> (sh + 1)) & 1u);
            }
        }

        // ---- exp2 (MUFU) + pack P into A-fragments
        unsigned ph[8][2];
#pragma unroll
        for (int nt = 0; nt < 8; ++nt) {
            float p0 = ex2f(s[nt][0]);
            float p1 = ex2f(s[nt][1]);
            float p2 = ex2f(s[nt][2]);
            float p3 = ex2f(s[nt][3]);
            rs0 += p0 + p1;
            rs1 += p2 + p3;
            ph[nt][0] = pack_h2(p0, p1);
            ph[nt][1] = pack_h2(p2, p3);
        }

        // ---- PV
#pragma unroll
        for (int kk = 0; kk < 4; ++kk) {
            const int kb = kk * 16;
            const unsigned a0 = ph[2 * kk][0];
            const unsigned a1 = ph[2 * kk][1];
            const unsigned a2 = ph[2 * kk + 1][0];
            const unsigned a3 = ph[2 * kk + 1][1];
#pragma unroll
            for (int p = 0; p < 4; ++p) {
                unsigned b0, b1, b2, b3;
                LDSM_X4_TRANS(b0, b1, b2, b3,
                              vb_l + bufb + (unsigned)(kb * (ROW_H * 2) + p * 32));
                MMA_F16(o[2 * p],     a0, a1, a2, a3, b0, b1);
                MMA_F16(o[2 * p + 1], a0, a1, a2, a3, b2, b3);
            }
        }

        ++bi; if (bi >= 3) bi = 0;
    }

    // epilogue
    rs0 += __shfl_xor_sync(0xffffffffu, rs0, 1);
    rs0 += __shfl_xor_sync(0xffffffffu, rs0, 2);
    rs1 += __shfl_xor_sync(0xffffffffu, rs1, 1);
    rs1 += __shfl_xor_sync(0xffffffffu, rs1, 2);
    const float inv0 = 1.0f / rs0;
    const float inv1 = 1.0f / rs1;

    float* og0 = out + ((size_t)b * S_ + q0 + m0 + r) * D_ + h * HD_;
    float* og1 = og0 + 8 * (size_t)D_;
#pragma unroll
    for (int nt = 0; nt < 8; ++nt) {
        const int col = nt * 8 + 2 * c;
        float2 w0; w0.x = o[nt][0] * inv0; w0.y = o[nt][1] * inv0;
        float2 w1; w1.x = o[nt][2] * inv1; w1.y = o[nt][3] * inv1;
        *(float2*)&og0[col] = w0;
        *(float2*)&og1[col] = w1;
    }
}

// ---------------- launch ----------------
extern "C" void kernel_launch(void* const* d_in, const int* in_sizes, int n_in,
                              void* d_out, int out_size) {
    (void)in_sizes; (void)n_in; (void)out_size;
    const float* x    = (const float*)d_in[0];
    const void*  mask = d_in[1];
    const float* Wq   = (const float*)d_in[2];
    const float* bq   = (const float*)d_in[3];
    const float* Wk   = (const float*)d_in[4];
    const float* bk   = (const float*)d_in[5];
    const float* Wv   = (const float*)d_in[6];
    const float* bv   = (const float*)d_in[7];
    float* out = (float*)d_out;

    detect_mask_kernel<<<1, 256>>>((const unsigned int*)mask);

    {
        const int warps = (int)(NMASK / 128);
        pack_mask_kernel<<<(warps * 32 + 255) / 256, 256>>>(mask);
    }

    dim3 ggrid(D_ / TBN, (B_ * S_) / TBM, 3);
    qkv_gemm_tc_kernel<<<ggrid, 256>>>(x, Wq, bq, Wk, bk, Wv, bv);

    const int smem_bytes = (AT_BM * ROW_H + 6 * KVH) * (int)sizeof(__half);
    cudaFuncSetAttribute(attn_tc_kernel, cudaFuncAttributeMaxDynamicSharedMemorySize, smem_bytes);
    dim3 agrid(S_ / AT_BM, H_, B_);
    attn_tc_kernel<<<agrid, 256, smem_bytes>>>(out);
}